// round 1
// baseline (speedup 1.0000x reference)
#include <cuda_runtime.h>
#include <math.h>

#define FULL 0xffffffffu

// ---------------- problem constants ----------------
constexpr int DIM   = 256;
constexpr int HEADS = 8;
constexpr int HD    = 32;
constexpr float SCALE_F = 0.17677669529663687f;  // 32^-0.5

constexpr int NX  = 6400;   // x tokens (80*80)
constexpr int NY  = 1024;   // y tokens per batch (32*32)
constexpr int BY  = 4;      // y batch
constexpr int NRX = 1600;   // reduced x tokens (40*40)
constexpr int NRY = 256;    // reduced y tokens per batch (16*16)

// ---------------- scratch (device globals; no allocation allowed) ----------------
__device__ float g_qx  [NX * DIM];
__device__ float g_qy  [BY * NY * DIM];
__device__ float g_red [(NRX + BY * NRY) * DIM];
__device__ float g_kvx [NRX * 2 * DIM];
__device__ float g_kvy [BY * NRY * 2 * DIM];
__device__ float g_kvym[NRY * 2 * DIM];
__device__ float g_ox  [NX * DIM];
__device__ float g_oy  [BY * NY * DIM];
__device__ float g_srwT[1024 * DIM];

// ---------------- weight transpose: sr_w[o,i,kh,kw] (o-major) -> wT[k=i*4+kh*2+kw][o] ----------------
__global__ void transpose_w_kernel(const float* __restrict__ srw, float* __restrict__ wT)
{
    int idx = blockIdx.x * 256 + threadIdx.x;   // over 256*1024
    int o = idx >> 10;
    int k = idx & 1023;
    wT[k * 256 + o] = srw[idx];
}

// ---------------- generic tiled SGEMM: C[M,N] = A[M,K] @ B[K,N] (+ bias[n]) ----------------
// block(16,16), 64x64 tile, K-tile 16, 4x4 per thread. Requires M%64==0, N%64==0, K%16==0.
__global__ void sgemm_kernel(const float* __restrict__ A, const float* __restrict__ B,
                             const float* __restrict__ bias, float* __restrict__ C,
                             int M, int N, int K)
{
    __shared__ float As[16][64];
    __shared__ float Bs[16][64];

    const int tx = threadIdx.x, ty = threadIdx.y;
    const int tid = ty * 16 + tx;
    const int rowBase = blockIdx.y * 64;
    const int colBase = blockIdx.x * 64;

    float acc[4][4] = {};

    for (int k0 = 0; k0 < K; k0 += 16) {
        // A tile: 64 rows x 16 k -> As[k][m]
        {
            int r  = tid >> 2;
            int cb = (tid & 3) * 4;
            float4 a4 = *(const float4*)&A[(size_t)(rowBase + r) * K + k0 + cb];
            As[cb + 0][r] = a4.x;
            As[cb + 1][r] = a4.y;
            As[cb + 2][r] = a4.z;
            As[cb + 3][r] = a4.w;
        }
        // B tile: 16 k x 64 n -> Bs[k][n]
        {
            int rb  = tid >> 4;
            int cb2 = (tid & 15) * 4;
            *(float4*)&Bs[rb][cb2] = *(const float4*)&B[(size_t)(k0 + rb) * N + colBase + cb2];
        }
        __syncthreads();

        #pragma unroll
        for (int kk = 0; kk < 16; kk++) {
            float4 a = *(float4*)&As[kk][ty * 4];
            float4 b = *(float4*)&Bs[kk][tx * 4];
            float av[4] = {a.x, a.y, a.z, a.w};
            float bv[4] = {b.x, b.y, b.z, b.w};
            #pragma unroll
            for (int i = 0; i < 4; i++)
                #pragma unroll
                for (int j = 0; j < 4; j++)
                    acc[i][j] += av[i] * bv[j];
        }
        __syncthreads();
    }

    #pragma unroll
    for (int i = 0; i < 4; i++) {
        int row = rowBase + ty * 4 + i;
        #pragma unroll
        for (int j = 0; j < 4; j++) {
            int col = colBase + tx * 4 + j;
            float v = acc[i][j];
            if (bias) v += bias[col];
            C[(size_t)row * N + col] = v;
        }
    }
}

// ---------------- SR conv as GEMM with on-the-fly im2col gather ----------------
// out[m, o] = sum_k X[gather(m,k)] * wT[k][o] + bias[o], K=1024, N=256
__global__ void conv_gemm_kernel(const float* __restrict__ X, const float* __restrict__ WT,
                                 const float* __restrict__ bias, float* __restrict__ C,
                                 int srcW, int redW, int srcTok, int redTok)
{
    __shared__ float As[16][64];
    __shared__ float Bs[16][64];

    const int tx = threadIdx.x, ty = threadIdx.y;
    const int tid = ty * 16 + tx;
    const int rowBase = blockIdx.y * 64;
    const int colBase = blockIdx.x * 64;

    // per-thread gather coordinates for its A-tile row
    const int r  = tid >> 2;
    const int cb = (tid & 3) * 4;
    const int m  = rowBase + r;
    const int b  = m / redTok;
    const int mm = m % redTok;
    const int oh = mm / redW;
    const int ow = mm % redW;
    const size_t srcBase = (size_t)b * srcTok * 256;

    float acc[4][4] = {};

    for (int k0 = 0; k0 < 1024; k0 += 16) {
        #pragma unroll
        for (int j = 0; j < 4; j++) {
            int k  = k0 + cb + j;
            int i  = k >> 2;
            int kh = (k >> 1) & 1;
            int kw = k & 1;
            int tok = (oh * 2 + kh) * srcW + (ow * 2 + kw);
            As[cb + j][r] = X[srcBase + (size_t)tok * 256 + i];
        }
        {
            int rb  = tid >> 4;
            int cb2 = (tid & 15) * 4;
            *(float4*)&Bs[rb][cb2] = *(const float4*)&WT[(size_t)(k0 + rb) * 256 + colBase + cb2];
        }
        __syncthreads();

        #pragma unroll
        for (int kk = 0; kk < 16; kk++) {
            float4 a = *(float4*)&As[kk][ty * 4];
            float4 b4 = *(float4*)&Bs[kk][tx * 4];
            float av[4] = {a.x, a.y, a.z, a.w};
            float bv[4] = {b4.x, b4.y, b4.z, b4.w};
            #pragma unroll
            for (int i = 0; i < 4; i++)
                #pragma unroll
                for (int j = 0; j < 4; j++)
                    acc[i][j] += av[i] * bv[j];
        }
        __syncthreads();
    }

    #pragma unroll
    for (int i = 0; i < 4; i++) {
        int row = rowBase + ty * 4 + i;
        #pragma unroll
        for (int j = 0; j < 4; j++) {
            int col = colBase + tx * 4 + j;
            C[(size_t)row * 256 + col] = acc[i][j] + bias[col];
        }
    }
}

// ---------------- LayerNorm over channel dim (256), in place ----------------
__global__ void ln_kernel(float* __restrict__ red, const float* __restrict__ g,
                          const float* __restrict__ b)
{
    const int t = blockIdx.x;
    const int c = threadIdx.x;
    __shared__ float sh[8];
    __shared__ float s_mean, s_rstd;

    float v = red[(size_t)t * 256 + c];

    float x = v;
    #pragma unroll
    for (int o = 16; o > 0; o >>= 1) x += __shfl_xor_sync(FULL, x, o);
    if ((c & 31) == 0) sh[c >> 5] = x;
    __syncthreads();
    if (c == 0) {
        float s = 0.f;
        #pragma unroll
        for (int i = 0; i < 8; i++) s += sh[i];
        s_mean = s * (1.0f / 256.0f);
    }
    __syncthreads();

    float d = v - s_mean;
    float x2 = d * d;
    #pragma unroll
    for (int o = 16; o > 0; o >>= 1) x2 += __shfl_xor_sync(FULL, x2, o);
    if ((c & 31) == 0) sh[c >> 5] = x2;
    __syncthreads();
    if (c == 0) {
        float s = 0.f;
        #pragma unroll
        for (int i = 0; i < 8; i++) s += sh[i];
        s_rstd = rsqrtf(s * (1.0f / 256.0f) + 1e-5f);
    }
    __syncthreads();

    red[(size_t)t * 256 + c] = d * s_rstd * g[c] + b[c];
}

// ---------------- batch mean of support KV ----------------
__global__ void meankv_kernel(const float* __restrict__ kvy, float* __restrict__ out)
{
    int idx = blockIdx.x * 256 + threadIdx.x;   // over NRY*512
    const int STRIDE = NRY * 2 * DIM;
    out[idx] = 0.25f * (kvy[idx] + kvy[idx + STRIDE] + kvy[idx + 2 * STRIDE] + kvy[idx + 3 * STRIDE]);
}

// ---------------- flash-style attention: warp per query, 32-key chunks ----------------
// Q layout [Nq, 256] (head h dims at h*32..), KV rows [*, 512]: k at h*32+d, v at 256+h*32+d.
// keys: first N1 rows from KV1, next N2 rows from KV2.  (N1+N2) % 32 == 0.
__global__ void attn_kernel(const float* __restrict__ Q, const float* __restrict__ KV1,
                            const float* __restrict__ KV2, float* __restrict__ O,
                            int N1, int N2)
{
    const int h    = blockIdx.y;
    const int warp = threadIdx.x >> 5;
    const int lane = threadIdx.x & 31;
    const int qi   = blockIdx.x * 4 + warp;

    __shared__ float Ks[32 * 33];
    __shared__ float Vs[32 * 33];

    const float qreg = Q[(size_t)qi * 256 + h * 32 + lane] * SCALE_F;
    float m = -1e30f, s = 0.f, acc = 0.f;

    const int total = N1 + N2;
    const int colT  = threadIdx.x & 31;
    const int r0    = threadIdx.x >> 5;

    for (int c0 = 0; c0 < total; c0 += 32) {
        // cooperative load of 32 keys (K and V), coalesced along channels
        #pragma unroll
        for (int i = 0; i < 8; i++) {
            int row = r0 + i * 4;
            int kg  = c0 + row;
            const float* base = (kg < N1) ? (KV1 + (size_t)kg * 512)
                                          : (KV2 + (size_t)(kg - N1) * 512);
            Ks[row * 33 + colT] = base[h * 32 + colT];
            Vs[row * 33 + colT] = base[256 + h * 32 + colT];
        }
        __syncthreads();

        // score for this lane's key
        float sc = 0.f;
        #pragma unroll
        for (int d = 0; d < 32; d++) {
            float qd = __shfl_sync(FULL, qreg, d);
            sc += qd * Ks[lane * 33 + d];
        }

        // online softmax update
        float cm = sc;
        #pragma unroll
        for (int o = 16; o > 0; o >>= 1) cm = fmaxf(cm, __shfl_xor_sync(FULL, cm, o));
        float Mn = fmaxf(m, cm);
        float p  = __expf(sc - Mn);
        float ps = p;
        #pragma unroll
        for (int o = 16; o > 0; o >>= 1) ps += __shfl_xor_sync(FULL, ps, o);
        float alpha = __expf(m - Mn);
        s   = s * alpha + ps;
        acc = acc * alpha;

        #pragma unroll
        for (int j = 0; j < 32; j++) {
            float pj = __shfl_sync(FULL, p, j);
            acc += pj * Vs[j * 33 + lane];
        }
        m = Mn;
        __syncthreads();
    }

    O[(size_t)qi * 256 + h * 32 + lane] = acc / s;
}

// ---------------- launch ----------------
extern "C" void kernel_launch(void* const* d_in, const int* in_sizes, int n_in,
                              void* d_out, int out_size)
{
    const float* x   = (const float*)d_in[0];
    const float* y   = (const float*)d_in[1];
    const float* Wq  = (const float*)d_in[2];
    const float* Wkv = (const float*)d_in[3];
    const float* srw = (const float*)d_in[4];
    const float* srb = (const float*)d_in[5];
    const float* lng = (const float*)d_in[6];
    const float* lnb = (const float*)d_in[7];
    const float* pw  = (const float*)d_in[8];
    const float* pb  = (const float*)d_in[9];
    float* out = (float*)d_out;

    float *qx, *qy, *red, *kvx, *kvy, *kvym, *ox, *oy, *srwT;
    cudaGetSymbolAddress((void**)&qx,   g_qx);
    cudaGetSymbolAddress((void**)&qy,   g_qy);
    cudaGetSymbolAddress((void**)&red,  g_red);
    cudaGetSymbolAddress((void**)&kvx,  g_kvx);
    cudaGetSymbolAddress((void**)&kvy,  g_kvy);
    cudaGetSymbolAddress((void**)&kvym, g_kvym);
    cudaGetSymbolAddress((void**)&ox,   g_ox);
    cudaGetSymbolAddress((void**)&oy,   g_oy);
    cudaGetSymbolAddress((void**)&srwT, g_srwT);

    const dim3 blk(16, 16);

    transpose_w_kernel<<<1024, 256>>>(srw, srwT);

    // Q projections
    sgemm_kernel<<<dim3(DIM / 64, NX / 64), blk>>>(x, Wq, nullptr, qx, NX, DIM, DIM);
    sgemm_kernel<<<dim3(DIM / 64, (BY * NY) / 64), blk>>>(y, Wq, nullptr, qy, BY * NY, DIM, DIM);

    // SR conv (as GEMM) + LN
    conv_gemm_kernel<<<dim3(DIM / 64, NRX / 64), blk>>>(x, srwT, srb, red, 80, 40, NX, NRX);
    conv_gemm_kernel<<<dim3(DIM / 64, (BY * NRY) / 64), blk>>>(y, srwT, srb, red + (size_t)NRX * DIM, 32, 16, NY, NRY);
    ln_kernel<<<NRX + BY * NRY, 256>>>(red, lng, lnb);

    // KV projections
    sgemm_kernel<<<dim3(2 * DIM / 64, NRX / 64), blk>>>(red, Wkv, nullptr, kvx, NRX, 2 * DIM, DIM);
    sgemm_kernel<<<dim3(2 * DIM / 64, (BY * NRY) / 64), blk>>>(red + (size_t)NRX * DIM, Wkv, nullptr, kvy, BY * NRY, 2 * DIM, DIM);

    // batch-mean support KV
    meankv_kernel<<<(NRY * 2 * DIM) / 256, 256>>>(kvy, kvym);

    // attention
    attn_kernel<<<dim3(NX / 4, HEADS), 128>>>(qx, kvx, kvym, ox, NRX, NRY);
    for (int b = 0; b < BY; b++) {
        attn_kernel<<<dim3(NY / 4, HEADS), 128>>>(qy + (size_t)b * NY * DIM, kvx,
                                                  kvy + (size_t)b * NRY * 2 * DIM,
                                                  oy + (size_t)b * NY * DIM, NRX, NRY);
    }

    // output projections straight into d_out (x_out, then y_out)
    sgemm_kernel<<<dim3(DIM / 64, NX / 64), blk>>>(ox, pw, pb, out, NX, DIM, DIM);
    sgemm_kernel<<<dim3(DIM / 64, (BY * NY) / 64), blk>>>(oy, pw, pb, out + (size_t)NX * DIM, BY * NY, DIM, DIM);
}

// round 3
// speedup vs baseline: 3.3355x; 3.3355x over previous
#include <cuda_runtime.h>
#include <math.h>

#define FULL 0xffffffffu

// ---------------- problem constants ----------------
constexpr int DIM   = 256;
constexpr int HEADS = 8;
constexpr int HD    = 32;
constexpr float SCALE_F = 0.17677669529663687f;  // 32^-0.5

constexpr int NX  = 6400;   // x tokens (80*80)
constexpr int NY  = 1024;   // y tokens per batch (32*32)
constexpr int BY  = 4;      // y batch
constexpr int NRX = 1600;   // reduced x tokens (40*40)
constexpr int NRY = 256;    // reduced y tokens per batch (16*16)

// ---------------- scratch (device globals; no allocation allowed) ----------------
__device__ float g_qx  [NX * DIM];
__device__ float g_qy  [BY * NY * DIM];
__device__ float g_red [(NRX + BY * NRY) * DIM];
__device__ float g_kvx [NRX * 2 * DIM];
__device__ float g_kvy [BY * NRY * 2 * DIM];
__device__ float g_kvym[NRY * 2 * DIM];
__device__ float g_ox  [NX * DIM];
__device__ float g_oy  [BY * NY * DIM];
__device__ float g_srwT[1024 * DIM];

// ---------------- weight transpose: sr_w[o,i,kh,kw] (o-major) -> wT[k=i*4+kh*2+kw][o] ----------------
__global__ void transpose_w_kernel(const float* __restrict__ srw, float* __restrict__ wT)
{
    int idx = blockIdx.x * 256 + threadIdx.x;   // over 256*1024
    int o = idx >> 10;
    int k = idx & 1023;
    wT[k * 256 + o] = srw[idx];
}

// ---------------- generic tiled SGEMM: C[M,N] = A[M,K] @ B[K,N] (+ bias[n]) ----------------
// block(16,16), 64x64 tile, K-tile 16, 4x4 per thread. Requires M%64==0, N%64==0, K%16==0.
__global__ void sgemm_kernel(const float* __restrict__ A, const float* __restrict__ B,
                             const float* __restrict__ bias, float* __restrict__ C,
                             int M, int N, int K)
{
    __shared__ float As[16][64];
    __shared__ float Bs[16][64];

    const int tx = threadIdx.x, ty = threadIdx.y;
    const int tid = ty * 16 + tx;
    const int rowBase = blockIdx.y * 64;
    const int colBase = blockIdx.x * 64;

    float acc[4][4] = {};

    for (int k0 = 0; k0 < K; k0 += 16) {
        {
            int r  = tid >> 2;
            int cb = (tid & 3) * 4;
            float4 a4 = *(const float4*)&A[(size_t)(rowBase + r) * K + k0 + cb];
            As[cb + 0][r] = a4.x;
            As[cb + 1][r] = a4.y;
            As[cb + 2][r] = a4.z;
            As[cb + 3][r] = a4.w;
        }
        {
            int rb  = tid >> 4;
            int cb2 = (tid & 15) * 4;
            *(float4*)&Bs[rb][cb2] = *(const float4*)&B[(size_t)(k0 + rb) * N + colBase + cb2];
        }
        __syncthreads();

        #pragma unroll
        for (int kk = 0; kk < 16; kk++) {
            float4 a = *(float4*)&As[kk][ty * 4];
            float4 b = *(float4*)&Bs[kk][tx * 4];
            float av[4] = {a.x, a.y, a.z, a.w};
            float bv[4] = {b.x, b.y, b.z, b.w};
            #pragma unroll
            for (int i = 0; i < 4; i++)
                #pragma unroll
                for (int j = 0; j < 4; j++)
                    acc[i][j] += av[i] * bv[j];
        }
        __syncthreads();
    }

    #pragma unroll
    for (int i = 0; i < 4; i++) {
        int row = rowBase + ty * 4 + i;
        #pragma unroll
        for (int j = 0; j < 4; j++) {
            int col = colBase + tx * 4 + j;
            float v = acc[i][j];
            if (bias) v += bias[col];
            C[(size_t)row * N + col] = v;
        }
    }
}

// ---------------- SR conv as GEMM with on-the-fly im2col gather ----------------
__global__ void conv_gemm_kernel(const float* __restrict__ X, const float* __restrict__ WT,
                                 const float* __restrict__ bias, float* __restrict__ C,
                                 int srcW, int redW, int srcTok, int redTok)
{
    __shared__ float As[16][64];
    __shared__ float Bs[16][64];

    const int tx = threadIdx.x, ty = threadIdx.y;
    const int tid = ty * 16 + tx;
    const int rowBase = blockIdx.y * 64;
    const int colBase = blockIdx.x * 64;

    const int r  = tid >> 2;
    const int cb = (tid & 3) * 4;
    const int m  = rowBase + r;
    const int b  = m / redTok;
    const int mm = m % redTok;
    const int oh = mm / redW;
    const int ow = mm % redW;
    const size_t srcBase = (size_t)b * srcTok * 256;

    float acc[4][4] = {};

    for (int k0 = 0; k0 < 1024; k0 += 16) {
        #pragma unroll
        for (int j = 0; j < 4; j++) {
            int k  = k0 + cb + j;
            int i  = k >> 2;
            int kh = (k >> 1) & 1;
            int kw = k & 1;
            int tok = (oh * 2 + kh) * srcW + (ow * 2 + kw);
            As[cb + j][r] = X[srcBase + (size_t)tok * 256 + i];
        }
        {
            int rb  = tid >> 4;
            int cb2 = (tid & 15) * 4;
            *(float4*)&Bs[rb][cb2] = *(const float4*)&WT[(size_t)(k0 + rb) * 256 + colBase + cb2];
        }
        __syncthreads();

        #pragma unroll
        for (int kk = 0; kk < 16; kk++) {
            float4 a = *(float4*)&As[kk][ty * 4];
            float4 b4 = *(float4*)&Bs[kk][tx * 4];
            float av[4] = {a.x, a.y, a.z, a.w};
            float bv[4] = {b4.x, b4.y, b4.z, b4.w};
            #pragma unroll
            for (int i = 0; i < 4; i++)
                #pragma unroll
                for (int j = 0; j < 4; j++)
                    acc[i][j] += av[i] * bv[j];
        }
        __syncthreads();
    }

    #pragma unroll
    for (int i = 0; i < 4; i++) {
        int row = rowBase + ty * 4 + i;
        #pragma unroll
        for (int j = 0; j < 4; j++) {
            int col = colBase + tx * 4 + j;
            C[(size_t)row * 256 + col] = acc[i][j] + bias[col];
        }
    }
}

// ---------------- LayerNorm over channel dim (256), in place ----------------
__global__ void ln_kernel(float* __restrict__ red, const float* __restrict__ g,
                          const float* __restrict__ b)
{
    const int t = blockIdx.x;
    const int c = threadIdx.x;
    __shared__ float sh[8];
    __shared__ float s_mean, s_rstd;

    float v = red[(size_t)t * 256 + c];

    float x = v;
    #pragma unroll
    for (int o = 16; o > 0; o >>= 1) x += __shfl_xor_sync(FULL, x, o);
    if ((c & 31) == 0) sh[c >> 5] = x;
    __syncthreads();
    if (c == 0) {
        float s = 0.f;
        #pragma unroll
        for (int i = 0; i < 8; i++) s += sh[i];
        s_mean = s * (1.0f / 256.0f);
    }
    __syncthreads();

    float d = v - s_mean;
    float x2 = d * d;
    #pragma unroll
    for (int o = 16; o > 0; o >>= 1) x2 += __shfl_xor_sync(FULL, x2, o);
    if ((c & 31) == 0) sh[c >> 5] = x2;
    __syncthreads();
    if (c == 0) {
        float s = 0.f;
        #pragma unroll
        for (int i = 0; i < 8; i++) s += sh[i];
        s_rstd = rsqrtf(s * (1.0f / 256.0f) + 1e-5f);
    }
    __syncthreads();

    red[(size_t)t * 256 + c] = d * s_rstd * g[c] + b[c];
}

// ---------------- batch mean of support KV ----------------
__global__ void meankv_kernel(const float* __restrict__ kvy, float* __restrict__ out)
{
    int idx = blockIdx.x * 256 + threadIdx.x;   // over NRY*512
    const int STRIDE = NRY * 2 * DIM;
    out[idx] = 0.25f * (kvy[idx] + kvy[idx + STRIDE] + kvy[idx + 2 * STRIDE] + kvy[idx + 3 * STRIDE]);
}

// ---------------- block-tiled flash attention ----------------
// 64 queries x 64-key chunks. Block of 256 threads; each thread: 4x4 of S, 4x2 of O.
// Padded shared strides are multiples of 4 floats so float4/float2 LDS stay aligned.
__global__ void __launch_bounds__(256) attn_tile_kernel(
    const float* __restrict__ Qg, const float* __restrict__ KV1,
    const float* __restrict__ KV2g, float* __restrict__ Og,
    int N1, int N2, int qTokStride, int kv2Stride)
{
    const int h = blockIdx.y;
    const int b = blockIdx.z;
    const float* Q   = Qg  + (size_t)b * qTokStride * 256;
    float*       O   = Og  + (size_t)b * qTokStride * 256;
    const float* KV2 = KV2g + (size_t)b * kv2Stride;

    const int tid = threadIdx.x;
    const int tx  = tid & 15;
    const int ty  = tid >> 4;
    const int q0  = blockIdx.x * 64;

    __shared__ float Qs[32][68];   // [d][q], stride 68 (16B-aligned rows)
    __shared__ float Ks[32][68];   // [d][k]
    __shared__ float Vs[64][34];   // [k][d], stride 34 (8B-aligned rows)
    __shared__ float Ps[64][68];   // [q][k]

    // load Q tile (pre-scaled)
    #pragma unroll
    for (int i = 0; i < 8; i++) {
        int e = tid + i * 256;
        int q = e >> 5, d = e & 31;
        Qs[d][q] = Q[(size_t)(q0 + q) * 256 + h * 32 + d] * SCALE_F;
    }

    float m[4], l[4], o[4][2];
    #pragma unroll
    for (int i = 0; i < 4; i++) {
        m[i] = -1e30f; l[i] = 0.f; o[i][0] = 0.f; o[i][1] = 0.f;
    }

    const int total = N1 + N2;
    for (int c0 = 0; c0 < total; c0 += 64) {
        // cooperative K/V chunk load (coalesced along channels)
        #pragma unroll
        for (int i = 0; i < 8; i++) {
            int e = tid + i * 256;
            int k = e >> 5, d = e & 31;
            int kg = c0 + k;
            const float* base = (kg < N1) ? (KV1 + (size_t)kg * 512)
                                          : (KV2 + (size_t)(kg - N1) * 512);
            Ks[d][k] = base[h * 32 + d];
            Vs[k][d] = base[256 + h * 32 + d];
        }
        __syncthreads();

        // S = Q @ K^T  (rows q=ty*4+i, cols k=tx*4+j)
        float s[4][4] = {};
        #pragma unroll
        for (int d = 0; d < 32; d++) {
            float4 a  = *(float4*)&Qs[d][ty * 4];
            float4 bk = *(float4*)&Ks[d][tx * 4];
            float av[4] = {a.x, a.y, a.z, a.w};
            float bv[4] = {bk.x, bk.y, bk.z, bk.w};
            #pragma unroll
            for (int i = 0; i < 4; i++)
                #pragma unroll
                for (int j = 0; j < 4; j++)
                    s[i][j] += av[i] * bv[j];
        }

        // online softmax (row reductions across the 16 tx lanes)
        #pragma unroll
        for (int i = 0; i < 4; i++) {
            float rm = fmaxf(fmaxf(s[i][0], s[i][1]), fmaxf(s[i][2], s[i][3]));
            #pragma unroll
            for (int off = 1; off < 16; off <<= 1)
                rm = fmaxf(rm, __shfl_xor_sync(FULL, rm, off, 16));
            float mn = fmaxf(m[i], rm);
            float alpha = __expf(m[i] - mn);
            m[i] = mn;
            float rs = 0.f;
            #pragma unroll
            for (int j = 0; j < 4; j++) {
                s[i][j] = __expf(s[i][j] - mn);
                rs += s[i][j];
            }
            #pragma unroll
            for (int off = 1; off < 16; off <<= 1)
                rs += __shfl_xor_sync(FULL, rs, off, 16);
            l[i] = l[i] * alpha + rs;
            o[i][0] *= alpha;
            o[i][1] *= alpha;
        }

        // stage P
        #pragma unroll
        for (int i = 0; i < 4; i++)
            *(float4*)&Ps[ty * 4 + i][tx * 4] = make_float4(s[i][0], s[i][1], s[i][2], s[i][3]);
        __syncthreads();

        // O += P @ V  (rows q=ty*4+i, cols d=tx*2, tx*2+1)
        #pragma unroll 4
        for (int k = 0; k < 64; k++) {
            float2 v = *(float2*)&Vs[k][tx * 2];
            #pragma unroll
            for (int i = 0; i < 4; i++) {
                float p = Ps[ty * 4 + i][k];
                o[i][0] += p * v.x;
                o[i][1] += p * v.y;
            }
        }
        __syncthreads();
    }

    #pragma unroll
    for (int i = 0; i < 4; i++) {
        float inv = 1.f / l[i];
        float2 r = make_float2(o[i][0] * inv, o[i][1] * inv);
        *(float2*)&O[(size_t)(q0 + ty * 4 + i) * 256 + h * 32 + tx * 2] = r;
    }
}

// ---------------- launch ----------------
extern "C" void kernel_launch(void* const* d_in, const int* in_sizes, int n_in,
                              void* d_out, int out_size)
{
    const float* x   = (const float*)d_in[0];
    const float* y   = (const float*)d_in[1];
    const float* Wq  = (const float*)d_in[2];
    const float* Wkv = (const float*)d_in[3];
    const float* srw = (const float*)d_in[4];
    const float* srb = (const float*)d_in[5];
    const float* lng = (const float*)d_in[6];
    const float* lnb = (const float*)d_in[7];
    const float* pw  = (const float*)d_in[8];
    const float* pb  = (const float*)d_in[9];
    float* out = (float*)d_out;

    float *qx, *qy, *red, *kvx, *kvy, *kvym, *ox, *oy, *srwT;
    cudaGetSymbolAddress((void**)&qx,   g_qx);
    cudaGetSymbolAddress((void**)&qy,   g_qy);
    cudaGetSymbolAddress((void**)&red,  g_red);
    cudaGetSymbolAddress((void**)&kvx,  g_kvx);
    cudaGetSymbolAddress((void**)&kvy,  g_kvy);
    cudaGetSymbolAddress((void**)&kvym, g_kvym);
    cudaGetSymbolAddress((void**)&ox,   g_ox);
    cudaGetSymbolAddress((void**)&oy,   g_oy);
    cudaGetSymbolAddress((void**)&srwT, g_srwT);

    const dim3 blk(16, 16);

    transpose_w_kernel<<<1024, 256>>>(srw, srwT);

    // Q projections
    sgemm_kernel<<<dim3(DIM / 64, NX / 64), blk>>>(x, Wq, nullptr, qx, NX, DIM, DIM);
    sgemm_kernel<<<dim3(DIM / 64, (BY * NY) / 64), blk>>>(y, Wq, nullptr, qy, BY * NY, DIM, DIM);

    // SR conv (as GEMM) + LN
    conv_gemm_kernel<<<dim3(DIM / 64, NRX / 64), blk>>>(x, srwT, srb, red, 80, 40, NX, NRX);
    conv_gemm_kernel<<<dim3(DIM / 64, (BY * NRY) / 64), blk>>>(y, srwT, srb, red + (size_t)NRX * DIM, 32, 16, NY, NRY);
    ln_kernel<<<NRX + BY * NRY, 256>>>(red, lng, lnb);

    // KV projections
    sgemm_kernel<<<dim3(2 * DIM / 64, NRX / 64), blk>>>(red, Wkv, nullptr, kvx, NRX, 2 * DIM, DIM);
    sgemm_kernel<<<dim3(2 * DIM / 64, (BY * NRY) / 64), blk>>>(red + (size_t)NRX * DIM, Wkv, nullptr, kvy, BY * NRY, 2 * DIM, DIM);

    // batch-mean support KV
    meankv_kernel<<<(NRY * 2 * DIM) / 256, 256>>>(kvy, kvym);

    // attention: x (1 batch) and y (4 batches merged via grid.z)
    attn_tile_kernel<<<dim3(NX / 64, HEADS, 1), 256>>>(qx, kvx, kvym, ox, NRX, NRY, 0, 0);
    attn_tile_kernel<<<dim3(NY / 64, HEADS, BY), 256>>>(qy, kvx, kvy, oy, NRX, NRY, NY, NRY * 2 * DIM);

    // output projections straight into d_out (x_out, then y_out)
    sgemm_kernel<<<dim3(DIM / 64, NX / 64), blk>>>(ox, pw, pb, out, NX, DIM, DIM);
    sgemm_kernel<<<dim3(DIM / 64, (BY * NY) / 64), blk>>>(oy, pw, pb, out + (size_t)NX * DIM, BY * NY, DIM, DIM);
}